// round 2
// baseline (speedup 1.0000x reference)
#include <cuda_runtime.h>
#include <math.h>

#define BX 32
#define BY 8
#define TPT_X 4           // outputs per thread, x
#define TPT_Y 4           // outputs per thread, y
#define TILE_W (BX * TPT_X)   // 128
#define TILE_H (BY * TPT_Y)   // 32
#define SM_W (TILE_W + 4)     // 132
#define SM_H (TILE_H + 4)     // 36

__global__ __launch_bounds__(BX * BY)
void hitmiss_kernel(const float* __restrict__ in,
                    const float* __restrict__ Kh,
                    const float* __restrict__ Km,
                    float* __restrict__ out,
                    int H, int W, int Hout, int Wout)
{
    __shared__ __align__(16) float tile[SM_H][SM_W];

    const int tid  = threadIdx.y * BX + threadIdx.x;
    const int col0 = blockIdx.x * TILE_W;
    const int row0 = blockIdx.y * TILE_H;

    // --- kernels into registers (warp-uniform broadcast loads) ---
    float kh[25], km[25];
#pragma unroll
    for (int i = 0; i < 25; ++i) {
        kh[i] = __ldg(Kh + i);
        km[i] = __ldg(Km + i);
    }

    // --- cooperative tile load: 33 float4 per row x 36 rows ---
    const int NW4 = SM_W / 4;          // 33
    const int NV  = NW4 * SM_H;        // 1188 float4 slots
    for (int idx = tid; idx < NV; idx += BX * BY) {
        int r  = idx / NW4;
        int c4 = idx - r * NW4;
        int gr = row0 + r; if (gr > H - 1) gr = H - 1;
        int gc = col0 + c4 * 4;
        float4 v;
        if (gc + 3 <= W - 1) {
            v = *reinterpret_cast<const float4*>(in + (size_t)gr * W + gc);
        } else {
            // boundary tile: clamp (only feeds never-stored outputs)
            int c0 = gc     < W - 1 ? gc     : W - 1;
            int c1 = gc + 1 < W - 1 ? gc + 1 : W - 1;
            int c2 = gc + 2 < W - 1 ? gc + 2 : W - 1;
            int c3 = gc + 3 < W - 1 ? gc + 3 : W - 1;
            const float* rowp = in + (size_t)gr * W;
            v.x = rowp[c0]; v.y = rowp[c1]; v.z = rowp[c2]; v.w = rowp[c3];
        }
        *reinterpret_cast<float4*>(&tile[r][c4 * 4]) = v;
    }
    __syncthreads();

    // --- 4x4 register-blocked hit-or-miss ---
    const int lx = threadIdx.x * TPT_X;   // 0..124, multiple of 4 -> aligned LDS.128
    const int ly = threadIdx.y * TPT_Y;   // 0..28

    float mn[TPT_Y * TPT_X], mx[TPT_Y * TPT_X];
#pragma unroll
    for (int i = 0; i < TPT_Y * TPT_X; ++i) {
        mn[i] =  INFINITY;
        mx[i] = -INFINITY;
    }

#pragma unroll
    for (int r = 0; r < TPT_Y + 4; ++r) {          // 8 input rows
        float w[TPT_X + 4];                         // 8-wide window row
        float4 a = *reinterpret_cast<const float4*>(&tile[ly + r][lx]);
        float4 b = *reinterpret_cast<const float4*>(&tile[ly + r][lx + 4]);
        w[0] = a.x; w[1] = a.y; w[2] = a.z; w[3] = a.w;
        w[4] = b.x; w[5] = b.y; w[6] = b.z; w[7] = b.w;

#pragma unroll
        for (int orow = 0; orow < TPT_Y; ++orow) {
            const int di = r - orow;
            if (di < 0 || di > 4) continue;          // compile-time pruned
#pragma unroll
            for (int dj = 0; dj < 5; ++dj) {
                const float khv = kh[di * 5 + dj];
                const float kmv = km[di * 5 + dj];
#pragma unroll
                for (int oc = 0; oc < TPT_X; ++oc) {
                    const float v = w[oc + dj];
                    const int   o = orow * TPT_X + oc;
                    mn[o] = fminf(mn[o], v - khv);   // FADD (fma pipe) + FMNMX (alu pipe)
                    mx[o] = fmaxf(mx[o], v - kmv);
                }
            }
        }
    }

    // --- stores: float4 fast path, scalar at right/bottom edges ---
    const int oc0 = col0 + lx;
    const int or0 = row0 + ly;
#pragma unroll
    for (int orow = 0; orow < TPT_Y; ++orow) {
        const int gro = or0 + orow;
        if (gro >= Hout) continue;
        float r0 = mn[orow * TPT_X + 0] - mx[orow * TPT_X + 0];
        float r1 = mn[orow * TPT_X + 1] - mx[orow * TPT_X + 1];
        float r2 = mn[orow * TPT_X + 2] - mx[orow * TPT_X + 2];
        float r3 = mn[orow * TPT_X + 3] - mx[orow * TPT_X + 3];
        float* orow_p = out + (size_t)gro * Wout;
        if (oc0 + 3 < Wout) {
            float4 o; o.x = r0; o.y = r1; o.z = r2; o.w = r3;
            *reinterpret_cast<float4*>(orow_p + oc0) = o;
        } else {
            if (oc0 + 0 < Wout) orow_p[oc0 + 0] = r0;
            if (oc0 + 1 < Wout) orow_p[oc0 + 1] = r1;
            if (oc0 + 2 < Wout) orow_p[oc0 + 2] = r2;
            if (oc0 + 3 < Wout) orow_p[oc0 + 3] = r3;
        }
    }
}

extern "C" void kernel_launch(void* const* d_in, const int* in_sizes, int n_in,
                              void* d_out, int out_size)
{
    const float* in = (const float*)d_in[0];
    const float* Kh = (const float*)d_in[1];
    const float* Km = (const float*)d_in[2];
    float* out = (float*)d_out;

    // H = W = sqrt(n_elements): 4096x4096 in the dataset, derived generically.
    const int H = (int)lround(sqrt((double)in_sizes[0]));
    const int W = H;
    const int Hout = H - 4;
    const int Wout = W - 4;

    dim3 block(BX, BY);
    dim3 grid((Wout + TILE_W - 1) / TILE_W, (Hout + TILE_H - 1) / TILE_H);
    hitmiss_kernel<<<grid, block>>>(in, Kh, Km, out, H, W, Hout, Wout);
}